// round 11
// baseline (speedup 1.0000x reference)
#include <cuda_runtime.h>

// DimeNetBlock, round 11: edge kernel repacked for occupancy.
// Lane owns col-pair (2*lane, 2*lane+1); W1 rows = 1 packed reg each (34 regs
// total vs 64+); features staged PRE-DUPLICATED in SMEM so inner loop is
// 8x LDS.128 (broadcast) + 16x fma.f32x2 per edge. launch_bounds(256,4).
// Pipeline: hist -> lookback-scan -> permute -> edge_gather -> node.

#define NNODE 100000
#define NEDGE 3200000
constexpr int EMB = 64;

typedef unsigned long long ull;

__device__ __align__(16) float g_S[(size_t)NNODE * 64];
__device__ int g_cnt[NNODE + 512];
__device__ int g_off[NNODE + 1];
__device__ int g_woff[NNODE];
__device__ int g_sorted[NEDGE];
__device__ unsigned int g_scanblk[256];

__device__ __forceinline__ float fsig(float x) {
    float e;
    asm("ex2.approx.f32 %0, %1;" : "=f"(e) : "f"(-1.4426950408889634f * x));
    float r;
    asm("rcp.approx.f32 %0, %1;" : "=f"(r) : "f"(1.0f + e));
    return r;
}

__device__ __forceinline__ ull pk2(float lo, float hi) {
    ull r; asm("mov.b64 %0, {%1, %2};" : "=l"(r) : "f"(lo), "f"(hi)); return r;
}
__device__ __forceinline__ float2 up2(ull v) {
    float2 f; asm("mov.b64 {%0, %1}, %2;" : "=f"(f.x), "=f"(f.y) : "l"(v)); return f;
}
__device__ __forceinline__ ull fma2(ull a, ull b, ull c) {
    ull d; asm("fma.rn.f32x2 %0, %1, %2, %3;" : "=l"(d) : "l"(a), "l"(b), "l"(c));
    return d;
}
__device__ __forceinline__ ull add2(ull a, ull b) {
    ull d; asm("add.rn.f32x2 %0, %1, %2;" : "=l"(d) : "l"(a), "l"(b)); return d;
}
__device__ __forceinline__ ull mul2(ull a, ull b) {
    ull d; asm("mul.rn.f32x2 %0, %1, %2;" : "=l"(d) : "l"(a), "l"(b)); return d;
}

// ---------------------------------------------------------------------------
// 1) histogram of row indices.
// ---------------------------------------------------------------------------
__global__ void hist_kernel(const int* __restrict__ eidx, int E) {
    int e = blockIdx.x * blockDim.x + threadIdx.x;
    if (e >= E) return;
    atomicAdd(&g_cnt[eidx[e]], 1);
}

// ---------------------------------------------------------------------------
// 2) decoupled-lookback exclusive scan; zeroes g_cnt for next replay.
// ---------------------------------------------------------------------------
__global__ void __launch_bounds__(512) scan_kernel(int N, int E) {
    __shared__ int s[512];
    __shared__ int blk_prefix;
    int b = blockIdx.x, t = threadIdx.x;
    int i = b * 512 + t;
    int v = (i < N) ? g_cnt[i] : 0;
    if (i < N) g_cnt[i] = 0;
    s[t] = v;
    __syncthreads();
    for (int d = 1; d < 512; d <<= 1) {
        int add = (t >= d) ? s[t - d] : 0;
        __syncthreads();
        s[t] += add;
        __syncthreads();
    }
    int incl = s[t];
    if (t == 0) {
        unsigned total = (unsigned)s[511];
        volatile unsigned* vb = g_scanblk;
        if (b == 0) {
            vb[0] = total | 0x80000000u;
            blk_prefix = 0;
        } else {
            vb[b] = total | 0x40000000u;
            unsigned run = 0;
            int p = b - 1;
            while (true) {
                unsigned f = vb[p];
                unsigned st = f >> 30;
                if (st == 0u) continue;
                run += f & 0x3FFFFFFFu;
                if (st >= 2u) break;
                p--;
            }
            vb[b] = (run + total) | 0x80000000u;
            blk_prefix = (int)run;
        }
    }
    __syncthreads();
    int ex = blk_prefix + incl - v;
    if (i < N) {
        g_off[i]  = ex;
        g_woff[i] = ex;
        if (i == N - 1) g_off[N] = ex + v;
    }
}

// ---------------------------------------------------------------------------
// 3) permute: scatter edge ids row-sorted; self-loops in top bit; block 0
//    resets lookback flags for next replay.
// ---------------------------------------------------------------------------
__global__ void permute_kernel(const int* __restrict__ eidx, int E) {
    if (blockIdx.x == 0 && threadIdx.x < 256) g_scanblk[threadIdx.x] = 0u;
    int e = blockIdx.x * blockDim.x + threadIdx.x;
    if (e >= E) return;
    int r = eidx[e];
    int c = eidx[(size_t)E + e];
    int p = atomicAdd(&g_woff[r], 1);
    g_sorted[p] = e | ((r == c) ? (int)0x80000000 : 0);
}

// ---------------------------------------------------------------------------
// 4) edge gather, warp per node, col-pair packing.
//    Tile: 8 k-pairs x 32 edges x 4 floats (f_{2kp} dup, f_{2kp+1} dup),
//    row stride 136 floats. Inner loop: 8 LDS.128 broadcast + 16 fma2.
// ---------------------------------------------------------------------------
#define ANG_A 3.14129265f            /* pi - 3e-4: constant angle */
#define ANG_CORR (1.57079633f - ANG_A)

__global__ void __launch_bounds__(256, 4) edge_gather_kernel(
    const float* __restrict__ rbf,
    const float* __restrict__ W1, const float* __restrict__ b1, int N)
{
    __shared__ __align__(16) float sfd[8][8 * 136];
    const int lane = threadIdx.x & 31;
    const int wid  = threadIdx.x >> 5;
    const int sub8 = lane >> 2;          // edge-within-8 for staging
    const int cmp4 = lane & 3;           // float4 k-group for staging
    float* sf = sfd[wid];

    ull w1p[16];
#pragma unroll
    for (int k = 0; k < 16; k++) {
        float2 w = *(const float2*)&W1[k * 64 + 2 * lane];
        w1p[k] = pk2(w.x, w.y);
    }
    ull bp, corrp;
    {
        float2 w16 = *(const float2*)&W1[16 * 64 + 2 * lane];
        float2 bv  = *(const float2*)&b1[2 * lane];
        bp    = pk2(fmaf(ANG_A, w16.x, bv.x), fmaf(ANG_A, w16.y, bv.y));
        corrp = pk2(ANG_CORR * w16.x, ANG_CORR * w16.y);
    }
    const ull halfp = pk2(0.5f, 0.5f);

    for (int n = blockIdx.x * 8 + wid; n < N; n += gridDim.x * 8) {
        int s0 = g_off[n], s1 = g_off[n + 1];
        ull acc = 0ull;

        for (int base = s0; base < s1; base += 32) {
            int m = min(32, s1 - base);
            int eidv = g_sorted[min(base + lane, s1 - 1)];
            unsigned slmask = __ballot_sync(0xffffffffu, eidv < 0);

#pragma unroll
            for (int r = 0; r < 4; r++) {
                int col = r * 8 + sub8;
                int es = __shfl_sync(0xffffffffu, eidv, col) & 0x7fffffff;
                float4 f4 = *(const float4*)&rbf[(size_t)es * 16 + 4 * cmp4];
                *(float4*)&sf[(2 * cmp4)     * 136 + 4 * col] =
                    make_float4(f4.x, f4.x, f4.y, f4.y);
                *(float4*)&sf[(2 * cmp4 + 1) * 136 + 4 * col] =
                    make_float4(f4.z, f4.z, f4.w, f4.w);
            }
            __syncwarp();

            for (int e = 0; e < m; e++) {
                ull h0 = bp, h1 = 0ull;
#pragma unroll
                for (int kp = 0; kp < 8; kp++) {
                    ulonglong2 ff =
                        *(const ulonglong2*)&sf[kp * 136 + 4 * e];
                    h0 = fma2(ff.x, w1p[2 * kp],     h0);
                    h1 = fma2(ff.y, w1p[2 * kp + 1], h1);
                }
                ull h = add2(h0, h1);
                if (slmask & (1u << e)) h = add2(h, corrp);  // self-loop (rare)
                // packed silu: s = h*sigmoid(h) = hh + hh*tanh(hh), hh = h/2
                ull hh = mul2(h, halfp);
                float2 u = up2(hh);
                float t0, t1;
                asm("tanh.approx.f32 %0, %1;" : "=f"(t0) : "f"(u.x));
                asm("tanh.approx.f32 %0, %1;" : "=f"(t1) : "f"(u.y));
                acc = add2(acc, fma2(hh, pk2(t0, t1), hh));
            }
            __syncwarp();
        }
        float2 a = up2(acc);
        *(float2*)&g_S[(size_t)n * 64 + 2 * lane] = a;
    }
}

// ---------------------------------------------------------------------------
// 5) node: warp processes 8 nodes; 48KB weights in SMEM (unchanged).
// ---------------------------------------------------------------------------
__global__ void __launch_bounds__(256) node_kernel(
    const float* __restrict__ x,
    const float* __restrict__ W2, const float* __restrict__ b2,
    const float* __restrict__ W3, const float* __restrict__ b3,
    const float* __restrict__ W4, const float* __restrict__ b4,
    float* __restrict__ out, int N)
{
    __shared__ __align__(16) float Ws[3 * 64 * 64];
    for (int i = threadIdx.x; i < 4096; i += 256) {
        Ws[i]        = W2[i];
        Ws[4096 + i] = W3[i];
        Ws[8192 + i] = W4[i];
    }
    __syncthreads();

    int lane = threadIdx.x & 31;
    int wid  = threadIdx.x >> 5;
    float2 bb2 = *(const float2*)&b2[2 * lane];
    float2 bb3 = *(const float2*)&b3[2 * lane];
    float2 bb4 = *(const float2*)&b4[2 * lane];

    for (int g = blockIdx.x * 8 + wid; g * 8 < N; g += gridDim.x * 8) {
        int n0 = g * 8;
        float2 v[8];
        float  dg[8];
#pragma unroll
        for (int t = 0; t < 8; t++) {
            int n = n0 + t;
            if (n < N) {
                v[t]  = *(const float2*)&g_S[(size_t)n * 64 + 2 * lane];
                dg[t] = (float)(g_off[n + 1] - g_off[n]);
            } else {
                v[t] = make_float2(0.f, 0.f); dg[t] = 0.f;
            }
        }

        float2 a[8];
#pragma unroll
        for (int t = 0; t < 8; t++)
            a[t] = make_float2(dg[t] * bb2.x, dg[t] * bb2.y);

#pragma unroll 4
        for (int kk = 0; kk < 32; kk++) {
            float2 w0 = *(const float2*)&Ws[(2 * kk)     * 64 + 2 * lane];
            float2 w1 = *(const float2*)&Ws[(2 * kk + 1) * 64 + 2 * lane];
#pragma unroll
            for (int t = 0; t < 8; t++) {
                float x0 = __shfl_sync(0xffffffffu, v[t].x, kk);
                float x1 = __shfl_sync(0xffffffffu, v[t].y, kk);
                a[t].x = fmaf(x0, w0.x, fmaf(x1, w1.x, a[t].x));
                a[t].y = fmaf(x0, w0.y, fmaf(x1, w1.y, a[t].y));
            }
        }

        float2 p[8];
#pragma unroll
        for (int t = 0; t < 8; t++) p[t] = bb3;
#pragma unroll 4
        for (int kk = 0; kk < 32; kk++) {
            float2 w0 = *(const float2*)&Ws[4096 + (2 * kk)     * 64 + 2 * lane];
            float2 w1 = *(const float2*)&Ws[4096 + (2 * kk + 1) * 64 + 2 * lane];
#pragma unroll
            for (int t = 0; t < 8; t++) {
                float x0 = __shfl_sync(0xffffffffu, a[t].x, kk);
                float x1 = __shfl_sync(0xffffffffu, a[t].y, kk);
                p[t].x = fmaf(x0, w0.x, fmaf(x1, w1.x, p[t].x));
                p[t].y = fmaf(x0, w0.y, fmaf(x1, w1.y, p[t].y));
            }
        }
#pragma unroll
        for (int t = 0; t < 8; t++) {
            p[t].x *= fsig(p[t].x);
            p[t].y *= fsig(p[t].y);
        }

        float2 q[8];
#pragma unroll
        for (int t = 0; t < 8; t++) q[t] = bb4;
#pragma unroll 4
        for (int kk = 0; kk < 32; kk++) {
            float2 w0 = *(const float2*)&Ws[8192 + (2 * kk)     * 64 + 2 * lane];
            float2 w1 = *(const float2*)&Ws[8192 + (2 * kk + 1) * 64 + 2 * lane];
#pragma unroll
            for (int t = 0; t < 8; t++) {
                float x0 = __shfl_sync(0xffffffffu, p[t].x, kk);
                float x1 = __shfl_sync(0xffffffffu, p[t].y, kk);
                q[t].x = fmaf(x0, w0.x, fmaf(x1, w1.x, q[t].x));
                q[t].y = fmaf(x0, w0.y, fmaf(x1, w1.y, q[t].y));
            }
        }
#pragma unroll
        for (int t = 0; t < 8; t++) {
            int n = n0 + t;
            if (n < N) {
                float2 xv = *(const float2*)&x[(size_t)n * 64 + 2 * lane];
                *(float2*)&out[(size_t)n * 64 + 2 * lane] =
                    make_float2(xv.x + q[t].x, xv.y + q[t].y);
            }
        }
    }
}

// ---------------------------------------------------------------------------
extern "C" void kernel_launch(void* const* d_in, const int* in_sizes, int n_in,
                              void* d_out, int out_size)
{
    const float* x   = (const float*)d_in[0];
    const float* rbf = (const float*)d_in[2];
    const int*   eidx = (const int*)d_in[3];
    const float* W1 = (const float*)d_in[4];
    const float* b1 = (const float*)d_in[5];
    const float* W2 = (const float*)d_in[6];
    const float* b2 = (const float*)d_in[7];
    const float* W3 = (const float*)d_in[8];
    const float* b3 = (const float*)d_in[9];
    const float* W4 = (const float*)d_in[10];
    const float* b4 = (const float*)d_in[11];
    float* out = (float*)d_out;

    int E = in_sizes[3] / 2;
    int N = in_sizes[0] / EMB;
    int nblk = (N + 511) / 512;

    hist_kernel<<<(E + 255) / 256, 256>>>(eidx, E);
    scan_kernel<<<nblk, 512>>>(N, E);
    permute_kernel<<<(E + 255) / 256, 256>>>(eidx, E);
    edge_gather_kernel<<<592, 256>>>(rbf, W1, b1, N);
    node_kernel<<<592, 256>>>(x, W2, b2, W3, b3, W4, b4, out, N);
}

// round 12
// speedup vs baseline: 1.0556x; 1.0556x over previous
#include <cuda_runtime.h>

// DimeNetBlock, round 12: tf32 mma.sync edge GEMM.
// Pipeline: hist(+slN reset) -> lookback-scan -> permute(+self-loop list)
//           -> edge_gather(tensor core) -> fixup(self-loops) -> node.

#define NNODE 100000
#define NEDGE 3200000
constexpr int EMB = 64;

#define ANG_A 3.14129265f            /* pi - 3e-4: constant angle */
#define PI_HALF 1.5707963267948966f

typedef unsigned long long ull;

__device__ __align__(16) float g_S[(size_t)NNODE * 64];
__device__ int g_cnt[NNODE + 512];
__device__ int g_off[NNODE + 1];
__device__ int g_woff[NNODE];
__device__ int g_sorted[NEDGE];
__device__ unsigned int g_scanblk[256];
__device__ int g_slN;
__device__ int g_slE[256];

__device__ __forceinline__ float fsig(float x) {
    float e;
    asm("ex2.approx.f32 %0, %1;" : "=f"(e) : "f"(-1.4426950408889634f * x));
    float r;
    asm("rcp.approx.f32 %0, %1;" : "=f"(r) : "f"(1.0f + e));
    return r;
}
__device__ __forceinline__ float fsilu_tanh(float x) {
    float h = 0.5f * x, t;
    asm("tanh.approx.f32 %0, %1;" : "=f"(t) : "f"(h));
    return fmaf(h, t, h);
}

__device__ __forceinline__ ull pk2(float lo, float hi) {
    ull r; asm("mov.b64 %0, {%1, %2};" : "=l"(r) : "f"(lo), "f"(hi)); return r;
}
__device__ __forceinline__ float2 up2(ull v) {
    float2 f; asm("mov.b64 {%0, %1}, %2;" : "=f"(f.x), "=f"(f.y) : "l"(v)); return f;
}
__device__ __forceinline__ ull fma2(ull a, ull b, ull c) {
    ull d; asm("fma.rn.f32x2 %0, %1, %2, %3;" : "=l"(d) : "l"(a), "l"(b), "l"(c));
    return d;
}
__device__ __forceinline__ ull add2(ull a, ull b) {
    ull d; asm("add.rn.f32x2 %0, %1, %2;" : "=l"(d) : "l"(a), "l"(b)); return d;
}
__device__ __forceinline__ ull mul2(ull a, ull b) {
    ull d; asm("mul.rn.f32x2 %0, %1, %2;" : "=l"(d) : "l"(a), "l"(b)); return d;
}
__device__ __forceinline__ unsigned f2tf(float f) {
    unsigned r; asm("cvt.rna.tf32.f32 %0, %1;" : "=r"(r) : "f"(f)); return r;
}
__device__ __forceinline__ void mma_tf32(
    float& d0, float& d1, float& d2, float& d3,
    unsigned a0, unsigned a1, unsigned a2, unsigned a3,
    unsigned b0, unsigned b1)
{
    asm volatile(
        "mma.sync.aligned.m16n8k8.row.col.f32.tf32.tf32.f32 "
        "{%0,%1,%2,%3}, {%4,%5,%6,%7}, {%8,%9}, {%0,%1,%2,%3};\n"
        : "+f"(d0), "+f"(d1), "+f"(d2), "+f"(d3)
        : "r"(a0), "r"(a1), "r"(a2), "r"(a3), "r"(b0), "r"(b1));
}
__device__ __forceinline__ ull silu2(ull h) {
    ull hh = mul2(h, pk2(0.5f, 0.5f));
    float2 u = up2(hh);
    float t0, t1;
    asm("tanh.approx.f32 %0, %1;" : "=f"(t0) : "f"(u.x));
    asm("tanh.approx.f32 %0, %1;" : "=f"(t1) : "f"(u.y));
    return fma2(hh, pk2(t0, t1), hh);
}

// ---------------------------------------------------------------------------
// 1) histogram; also resets the self-loop list counter for this replay.
// ---------------------------------------------------------------------------
__global__ void hist_kernel(const int* __restrict__ eidx, int E) {
    if (blockIdx.x == 0 && threadIdx.x == 0) g_slN = 0;
    int e = blockIdx.x * blockDim.x + threadIdx.x;
    if (e >= E) return;
    atomicAdd(&g_cnt[eidx[e]], 1);
}

// ---------------------------------------------------------------------------
// 2) decoupled-lookback exclusive scan; zeroes g_cnt for next replay.
// ---------------------------------------------------------------------------
__global__ void __launch_bounds__(512) scan_kernel(int N, int E) {
    __shared__ int s[512];
    __shared__ int blk_prefix;
    int b = blockIdx.x, t = threadIdx.x;
    int i = b * 512 + t;
    int v = (i < N) ? g_cnt[i] : 0;
    if (i < N) g_cnt[i] = 0;
    s[t] = v;
    __syncthreads();
    for (int d = 1; d < 512; d <<= 1) {
        int add = (t >= d) ? s[t - d] : 0;
        __syncthreads();
        s[t] += add;
        __syncthreads();
    }
    int incl = s[t];
    if (t == 0) {
        unsigned total = (unsigned)s[511];
        volatile unsigned* vb = g_scanblk;
        if (b == 0) {
            vb[0] = total | 0x80000000u;
            blk_prefix = 0;
        } else {
            vb[b] = total | 0x40000000u;
            unsigned run = 0;
            int p = b - 1;
            while (true) {
                unsigned f = vb[p];
                unsigned st = f >> 30;
                if (st == 0u) continue;
                run += f & 0x3FFFFFFFu;
                if (st >= 2u) break;
                p--;
            }
            vb[b] = (run + total) | 0x80000000u;
            blk_prefix = (int)run;
        }
    }
    __syncthreads();
    int ex = blk_prefix + incl - v;
    if (i < N) {
        g_off[i]  = ex;
        g_woff[i] = ex;
        if (i == N - 1) g_off[N] = ex + v;
    }
}

// ---------------------------------------------------------------------------
// 3) permute: row-sorted edge ids; self-loops appended to g_slE; block 0
//    resets lookback flags for next replay.
// ---------------------------------------------------------------------------
__global__ void permute_kernel(const int* __restrict__ eidx, int E) {
    if (blockIdx.x == 0 && threadIdx.x < 256) g_scanblk[threadIdx.x] = 0u;
    int e = blockIdx.x * blockDim.x + threadIdx.x;
    if (e >= E) return;
    int r = eidx[e];
    int c = eidx[(size_t)E + e];
    int p = atomicAdd(&g_woff[r], 1);
    g_sorted[p] = e;
    if (r == c) {
        int q = atomicAdd(&g_slN, 1);
        if (q < 256) g_slE[q] = e;
    }
}

// ---------------------------------------------------------------------------
// 4) edge gather via tf32 mma.sync (warp per node).
//    A = [32 edges x 16 feat] tile (stride 20, conflict-free), B = W1 frags
//    in regs, bias' = b1 + ANG_A*W1[16] in SMEM. Per chunk: 32 mma, packed
//    silu + predicated accumulate, shfl-reduce per node at the end.
// ---------------------------------------------------------------------------
__global__ void __launch_bounds__(256, 3) edge_gather_kernel(
    const float* __restrict__ rbf,
    const float* __restrict__ W1, const float* __restrict__ b1, int N)
{
    __shared__ __align__(16) float tilebuf[8][32 * 20];
    __shared__ __align__(8) float sbias[64];
    const int lane = threadIdx.x & 31;
    const int wid  = threadIdx.x >> 5;
    const int gid  = lane >> 2;      // groupID   (0..7)
    const int tig  = lane & 3;       // thread-in-group (0..3)
    float* tf = tilebuf[wid];

    if (threadIdx.x < 64)
        sbias[threadIdx.x] =
            fmaf(ANG_A, W1[16 * 64 + threadIdx.x], b1[threadIdx.x]);

    // B fragments: n = nt*8 + gid; k = kt*8 + tig (+4)
    unsigned Bf[8][2][2];
#pragma unroll
    for (int nt = 0; nt < 8; nt++) {
        int n = nt * 8 + gid;
#pragma unroll
        for (int kt = 0; kt < 2; kt++) {
            Bf[nt][kt][0] = f2tf(W1[(kt * 8 + tig) * 64 + n]);
            Bf[nt][kt][1] = f2tf(W1[(kt * 8 + tig + 4) * 64 + n]);
        }
    }
    __syncthreads();

    for (int n = blockIdx.x * 8 + wid; n < N; n += gridDim.x * 8) {
        int s0 = g_off[n], s1 = g_off[n + 1];
        ull acc[8];
#pragma unroll
        for (int i = 0; i < 8; i++) acc[i] = 0ull;

        for (int base = s0; base < s1; base += 32) {
            int m = min(32, s1 - base);
            int eidv = g_sorted[min(base + lane, s1 - 1)];

            // stage features: edge col = r*8+gid, k-group = 4*tig
#pragma unroll
            for (int r = 0; r < 4; r++) {
                int col = r * 8 + gid;
                int es = __shfl_sync(0xffffffffu, eidv, col);
                float4 f4 = *(const float4*)&rbf[(size_t)es * 16 + 4 * tig];
                *(float4*)&tf[col * 20 + 4 * tig] = f4;
            }
            __syncwarp();

#pragma unroll
            for (int mt = 0; mt < 2; mt++) {
                int r0 = mt * 16 + gid;
                bool p0 = (r0 < m), p1 = (r0 + 8 < m);
                unsigned a[2][4];
#pragma unroll
                for (int kt = 0; kt < 2; kt++) {
                    a[kt][0] = f2tf(tf[r0       * 20 + kt * 8 + tig]);
                    a[kt][1] = f2tf(tf[(r0 + 8) * 20 + kt * 8 + tig]);
                    a[kt][2] = f2tf(tf[r0       * 20 + kt * 8 + tig + 4]);
                    a[kt][3] = f2tf(tf[(r0 + 8) * 20 + kt * 8 + tig + 4]);
                }
#pragma unroll
                for (int nt = 0; nt < 8; nt++) {
                    float d0 = 0.f, d1 = 0.f, d2 = 0.f, d3 = 0.f;
                    mma_tf32(d0, d1, d2, d3,
                             a[0][0], a[0][1], a[0][2], a[0][3],
                             Bf[nt][0][0], Bf[nt][0][1]);
                    mma_tf32(d0, d1, d2, d3,
                             a[1][0], a[1][1], a[1][2], a[1][3],
                             Bf[nt][1][0], Bf[nt][1][1]);
                    ull bp = *(const ull*)&sbias[nt * 8 + 2 * tig];
                    ull v0 = silu2(add2(pk2(d0, d1), bp));
                    ull v1 = silu2(add2(pk2(d2, d3), bp));
                    if (p0) acc[nt] = add2(acc[nt], v0);
                    if (p1) acc[nt] = add2(acc[nt], v1);
                }
            }
            __syncwarp();
        }

        // reduce over the 8 gid lanes holding each column pair
#pragma unroll
        for (int nt = 0; nt < 8; nt++) {
            float2 av = up2(acc[nt]);
#pragma unroll
            for (int d = 4; d < 32; d <<= 1) {
                av.x += __shfl_xor_sync(0xffffffffu, av.x, d);
                av.y += __shfl_xor_sync(0xffffffffu, av.y, d);
            }
            acc[nt] = pk2(av.x, av.y);
        }
        if (gid == 0) {
#pragma unroll
            for (int nt = 0; nt < 8; nt++)
                *(float2*)&g_S[(size_t)n * 64 + nt * 8 + 2 * tig] = up2(acc[nt]);
        }
    }
}

// ---------------------------------------------------------------------------
// 4b) self-loop fixup (rare, ~32 edges): replace const-angle contribution
//     with the exact pi/2 one. Runs after edge_gather, before node.
// ---------------------------------------------------------------------------
__global__ void fixup_kernel(
    const float* __restrict__ rbf, const int* __restrict__ eidx,
    const float* __restrict__ W1, const float* __restrict__ b1, int E)
{
    int nsl = min(g_slN, 256);
    int w = threadIdx.x >> 5, lane = threadIdx.x & 31;
    for (int i = blockIdx.x * 8 + w; i < nsl; i += gridDim.x * 8) {
        int e = g_slE[i];
        int r = eidx[e];
        int c0 = 2 * lane, c1 = 2 * lane + 1;
        float h0 = b1[c0], h1 = b1[c1];
        for (int k = 0; k < 16; k++) {
            float f = rbf[(size_t)e * 16 + k];
            h0 = fmaf(f, W1[k * 64 + c0], h0);
            h1 = fmaf(f, W1[k * 64 + c1], h1);
        }
        float wa = W1[16 * 64 + c0], wb = W1[16 * 64 + c1];
        float d0 = fsilu_tanh(fmaf(PI_HALF, wa, h0)) -
                   fsilu_tanh(fmaf(ANG_A,  wa, h0));
        float d1 = fsilu_tanh(fmaf(PI_HALF, wb, h1)) -
                   fsilu_tanh(fmaf(ANG_A,  wb, h1));
        atomicAdd(&g_S[(size_t)r * 64 + c0], d0);
        atomicAdd(&g_S[(size_t)r * 64 + c1], d1);
    }
}

// ---------------------------------------------------------------------------
// 5) node: warp processes 8 nodes; 48KB weights in SMEM (unchanged).
// ---------------------------------------------------------------------------
__global__ void __launch_bounds__(256) node_kernel(
    const float* __restrict__ x,
    const float* __restrict__ W2, const float* __restrict__ b2,
    const float* __restrict__ W3, const float* __restrict__ b3,
    const float* __restrict__ W4, const float* __restrict__ b4,
    float* __restrict__ out, int N)
{
    __shared__ __align__(16) float Ws[3 * 64 * 64];
    for (int i = threadIdx.x; i < 4096; i += 256) {
        Ws[i]        = W2[i];
        Ws[4096 + i] = W3[i];
        Ws[8192 + i] = W4[i];
    }
    __syncthreads();

    int lane = threadIdx.x & 31;
    int wid  = threadIdx.x >> 5;
    float2 bb2 = *(const float2*)&b2[2 * lane];
    float2 bb3 = *(const float2*)&b3[2 * lane];
    float2 bb4 = *(const float2*)&b4[2 * lane];

    for (int g = blockIdx.x * 8 + wid; g * 8 < N; g += gridDim.x * 8) {
        int n0 = g * 8;
        float2 v[8];
        float  dg[8];
#pragma unroll
        for (int t = 0; t < 8; t++) {
            int n = n0 + t;
            if (n < N) {
                v[t]  = *(const float2*)&g_S[(size_t)n * 64 + 2 * lane];
                dg[t] = (float)(g_off[n + 1] - g_off[n]);
            } else {
                v[t] = make_float2(0.f, 0.f); dg[t] = 0.f;
            }
        }

        float2 a[8];
#pragma unroll
        for (int t = 0; t < 8; t++)
            a[t] = make_float2(dg[t] * bb2.x, dg[t] * bb2.y);

#pragma unroll 4
        for (int kk = 0; kk < 32; kk++) {
            float2 w0 = *(const float2*)&Ws[(2 * kk)     * 64 + 2 * lane];
            float2 w1 = *(const float2*)&Ws[(2 * kk + 1) * 64 + 2 * lane];
#pragma unroll
            for (int t = 0; t < 8; t++) {
                float x0 = __shfl_sync(0xffffffffu, v[t].x, kk);
                float x1 = __shfl_sync(0xffffffffu, v[t].y, kk);
                a[t].x = fmaf(x0, w0.x, fmaf(x1, w1.x, a[t].x));
                a[t].y = fmaf(x0, w0.y, fmaf(x1, w1.y, a[t].y));
            }
        }

        float2 p[8];
#pragma unroll
        for (int t = 0; t < 8; t++) p[t] = bb3;
#pragma unroll 4
        for (int kk = 0; kk < 32; kk++) {
            float2 w0 = *(const float2*)&Ws[4096 + (2 * kk)     * 64 + 2 * lane];
            float2 w1 = *(const float2*)&Ws[4096 + (2 * kk + 1) * 64 + 2 * lane];
#pragma unroll
            for (int t = 0; t < 8; t++) {
                float x0 = __shfl_sync(0xffffffffu, a[t].x, kk);
                float x1 = __shfl_sync(0xffffffffu, a[t].y, kk);
                p[t].x = fmaf(x0, w0.x, fmaf(x1, w1.x, p[t].x));
                p[t].y = fmaf(x0, w0.y, fmaf(x1, w1.y, p[t].y));
            }
        }
#pragma unroll
        for (int t = 0; t < 8; t++) {
            p[t].x *= fsig(p[t].x);
            p[t].y *= fsig(p[t].y);
        }

        float2 q[8];
#pragma unroll
        for (int t = 0; t < 8; t++) q[t] = bb4;
#pragma unroll 4
        for (int kk = 0; kk < 32; kk++) {
            float2 w0 = *(const float2*)&Ws[8192 + (2 * kk)     * 64 + 2 * lane];
            float2 w1 = *(const float2*)&Ws[8192 + (2 * kk + 1) * 64 + 2 * lane];
#pragma unroll
            for (int t = 0; t < 8; t++) {
                float x0 = __shfl_sync(0xffffffffu, p[t].x, kk);
                float x1 = __shfl_sync(0xffffffffu, p[t].y, kk);
                q[t].x = fmaf(x0, w0.x, fmaf(x1, w1.x, q[t].x));
                q[t].y = fmaf(x0, w0.y, fmaf(x1, w1.y, q[t].y));
            }
        }
#pragma unroll
        for (int t = 0; t < 8; t++) {
            int n = n0 + t;
            if (n < N) {
                float2 xv = *(const float2*)&x[(size_t)n * 64 + 2 * lane];
                *(float2*)&out[(size_t)n * 64 + 2 * lane] =
                    make_float2(xv.x + q[t].x, xv.y + q[t].y);
            }
        }
    }
}

// ---------------------------------------------------------------------------
extern "C" void kernel_launch(void* const* d_in, const int* in_sizes, int n_in,
                              void* d_out, int out_size)
{
    const float* x   = (const float*)d_in[0];
    const float* rbf = (const float*)d_in[2];
    const int*   eidx = (const int*)d_in[3];
    const float* W1 = (const float*)d_in[4];
    const float* b1 = (const float*)d_in[5];
    const float* W2 = (const float*)d_in[6];
    const float* b2 = (const float*)d_in[7];
    const float* W3 = (const float*)d_in[8];
    const float* b3 = (const float*)d_in[9];
    const float* W4 = (const float*)d_in[10];
    const float* b4 = (const float*)d_in[11];
    float* out = (float*)d_out;

    int E = in_sizes[3] / 2;
    int N = in_sizes[0] / EMB;
    int nblk = (N + 511) / 512;

    hist_kernel<<<(E + 255) / 256, 256>>>(eidx, E);
    scan_kernel<<<nblk, 512>>>(N, E);
    permute_kernel<<<(E + 255) / 256, 256>>>(eidx, E);
    edge_gather_kernel<<<592, 256>>>(rbf, W1, b1, N);
    fixup_kernel<<<4, 256>>>(rbf, eidx, W1, b1, E);
    node_kernel<<<592, 256>>>(x, W2, b2, W3, b3, W4, b4, out, N);
}

// round 13
// speedup vs baseline: 1.1815x; 1.1193x over previous
#include <cuda_runtime.h>

// DimeNetBlock, round 13: tf32 mma edge GEMM with 64-edge staging waves
// (double MLP, half the syncs). Pipeline: hist -> lookback-scan ->
// permute(+self-loop list) -> edge_gather -> fixup -> node.

#define NNODE 100000
#define NEDGE 3200000
constexpr int EMB = 64;

#define ANG_A 3.14129265f            /* pi - 3e-4: constant angle */
#define PI_HALF 1.5707963267948966f

typedef unsigned long long ull;

__device__ __align__(16) float g_S[(size_t)NNODE * 64];
__device__ int g_cnt[NNODE + 512];
__device__ int g_off[NNODE + 1];
__device__ int g_woff[NNODE];
__device__ int g_sorted[NEDGE];
__device__ unsigned int g_scanblk[256];
__device__ int g_slN;
__device__ int g_slE[256];

__device__ __forceinline__ float fsig(float x) {
    float e;
    asm("ex2.approx.f32 %0, %1;" : "=f"(e) : "f"(-1.4426950408889634f * x));
    float r;
    asm("rcp.approx.f32 %0, %1;" : "=f"(r) : "f"(1.0f + e));
    return r;
}
__device__ __forceinline__ float fsilu_tanh(float x) {
    float h = 0.5f * x, t;
    asm("tanh.approx.f32 %0, %1;" : "=f"(t) : "f"(h));
    return fmaf(h, t, h);
}

__device__ __forceinline__ ull pk2(float lo, float hi) {
    ull r; asm("mov.b64 %0, {%1, %2};" : "=l"(r) : "f"(lo), "f"(hi)); return r;
}
__device__ __forceinline__ float2 up2(ull v) {
    float2 f; asm("mov.b64 {%0, %1}, %2;" : "=f"(f.x), "=f"(f.y) : "l"(v)); return f;
}
__device__ __forceinline__ ull fma2(ull a, ull b, ull c) {
    ull d; asm("fma.rn.f32x2 %0, %1, %2, %3;" : "=l"(d) : "l"(a), "l"(b), "l"(c));
    return d;
}
__device__ __forceinline__ ull add2(ull a, ull b) {
    ull d; asm("add.rn.f32x2 %0, %1, %2;" : "=l"(d) : "l"(a), "l"(b)); return d;
}
__device__ __forceinline__ ull mul2(ull a, ull b) {
    ull d; asm("mul.rn.f32x2 %0, %1, %2;" : "=l"(d) : "l"(a), "l"(b)); return d;
}
__device__ __forceinline__ unsigned f2tf(float f) {
    unsigned r; asm("cvt.rna.tf32.f32 %0, %1;" : "=r"(r) : "f"(f)); return r;
}
__device__ __forceinline__ void mma_tf32(
    float& d0, float& d1, float& d2, float& d3,
    unsigned a0, unsigned a1, unsigned a2, unsigned a3,
    unsigned b0, unsigned b1)
{
    asm volatile(
        "mma.sync.aligned.m16n8k8.row.col.f32.tf32.tf32.f32 "
        "{%0,%1,%2,%3}, {%4,%5,%6,%7}, {%8,%9}, {%0,%1,%2,%3};\n"
        : "+f"(d0), "+f"(d1), "+f"(d2), "+f"(d3)
        : "r"(a0), "r"(a1), "r"(a2), "r"(a3), "r"(b0), "r"(b1));
}
__device__ __forceinline__ ull silu2(ull h) {
    ull hh = mul2(h, pk2(0.5f, 0.5f));
    float2 u = up2(hh);
    float t0, t1;
    asm("tanh.approx.f32 %0, %1;" : "=f"(t0) : "f"(u.x));
    asm("tanh.approx.f32 %0, %1;" : "=f"(t1) : "f"(u.y));
    return fma2(hh, pk2(t0, t1), hh);
}

// ---------------------------------------------------------------------------
// 1) histogram; also resets the self-loop list counter for this replay.
// ---------------------------------------------------------------------------
__global__ void hist_kernel(const int* __restrict__ eidx, int E) {
    if (blockIdx.x == 0 && threadIdx.x == 0) g_slN = 0;
    int e = blockIdx.x * blockDim.x + threadIdx.x;
    if (e >= E) return;
    atomicAdd(&g_cnt[eidx[e]], 1);
}

// ---------------------------------------------------------------------------
// 2) decoupled-lookback exclusive scan; zeroes g_cnt for next replay.
// ---------------------------------------------------------------------------
__global__ void __launch_bounds__(512) scan_kernel(int N, int E) {
    __shared__ int s[512];
    __shared__ int blk_prefix;
    int b = blockIdx.x, t = threadIdx.x;
    int i = b * 512 + t;
    int v = (i < N) ? g_cnt[i] : 0;
    if (i < N) g_cnt[i] = 0;
    s[t] = v;
    __syncthreads();
    for (int d = 1; d < 512; d <<= 1) {
        int add = (t >= d) ? s[t - d] : 0;
        __syncthreads();
        s[t] += add;
        __syncthreads();
    }
    int incl = s[t];
    if (t == 0) {
        unsigned total = (unsigned)s[511];
        volatile unsigned* vb = g_scanblk;
        if (b == 0) {
            vb[0] = total | 0x80000000u;
            blk_prefix = 0;
        } else {
            vb[b] = total | 0x40000000u;
            unsigned run = 0;
            int p = b - 1;
            while (true) {
                unsigned f = vb[p];
                unsigned st = f >> 30;
                if (st == 0u) continue;
                run += f & 0x3FFFFFFFu;
                if (st >= 2u) break;
                p--;
            }
            vb[b] = (run + total) | 0x80000000u;
            blk_prefix = (int)run;
        }
    }
    __syncthreads();
    int ex = blk_prefix + incl - v;
    if (i < N) {
        g_off[i]  = ex;
        g_woff[i] = ex;
        if (i == N - 1) g_off[N] = ex + v;
    }
}

// ---------------------------------------------------------------------------
// 3) permute: row-sorted edge ids; self-loops appended to g_slE; block 0
//    resets lookback flags for next replay.
// ---------------------------------------------------------------------------
__global__ void permute_kernel(const int* __restrict__ eidx, int E) {
    if (blockIdx.x == 0 && threadIdx.x < 256) g_scanblk[threadIdx.x] = 0u;
    int e = blockIdx.x * blockDim.x + threadIdx.x;
    if (e >= E) return;
    int r = eidx[e];
    int c = eidx[(size_t)E + e];
    int p = atomicAdd(&g_woff[r], 1);
    g_sorted[p] = e;
    if (r == c) {
        int q = atomicAdd(&g_slN, 1);
        if (q < 256) g_slE[q] = e;
    }
}

// ---------------------------------------------------------------------------
// 4) edge gather via tf32 mma.sync (warp per node), 64-edge staging waves.
// ---------------------------------------------------------------------------
__global__ void __launch_bounds__(256, 3) edge_gather_kernel(
    const float* __restrict__ rbf,
    const float* __restrict__ W1, const float* __restrict__ b1, int N)
{
    __shared__ __align__(16) float tilebuf[8][64 * 20];
    __shared__ __align__(8) float sbias[64];
    const int lane = threadIdx.x & 31;
    const int wid  = threadIdx.x >> 5;
    const int gid  = lane >> 2;
    const int tig  = lane & 3;
    float* tf = tilebuf[wid];

    if (threadIdx.x < 64)
        sbias[threadIdx.x] =
            fmaf(ANG_A, W1[16 * 64 + threadIdx.x], b1[threadIdx.x]);

    unsigned Bf[8][2][2];
#pragma unroll
    for (int nt = 0; nt < 8; nt++) {
        int n = nt * 8 + gid;
#pragma unroll
        for (int kt = 0; kt < 2; kt++) {
            Bf[nt][kt][0] = f2tf(W1[(kt * 8 + tig) * 64 + n]);
            Bf[nt][kt][1] = f2tf(W1[(kt * 8 + tig + 4) * 64 + n]);
        }
    }
    __syncthreads();

    for (int n = blockIdx.x * 8 + wid; n < N; n += gridDim.x * 8) {
        int s0 = g_off[n], s1 = g_off[n + 1];
        ull acc[8];
#pragma unroll
        for (int i = 0; i < 8; i++) acc[i] = 0ull;

        for (int base = s0; base < s1; base += 64) {
            int m = min(64, s1 - base);
            int eA = g_sorted[min(base + lane,      s1 - 1)];
            int eB = g_sorted[min(base + 32 + lane, s1 - 1)];

#pragma unroll
            for (int r = 0; r < 4; r++) {
                int col = r * 8 + gid;
                int es = __shfl_sync(0xffffffffu, eA, col);
                float4 f4 = *(const float4*)&rbf[(size_t)es * 16 + 4 * tig];
                *(float4*)&tf[col * 20 + 4 * tig] = f4;
            }
#pragma unroll
            for (int r = 4; r < 8; r++) {
                int col = r * 8 + gid;
                int es = __shfl_sync(0xffffffffu, eB, col - 32);
                float4 f4 = *(const float4*)&rbf[(size_t)es * 16 + 4 * tig];
                *(float4*)&tf[col * 20 + 4 * tig] = f4;
            }
            __syncwarp();

            int nmt = (m + 15) >> 4;     // warp-uniform tile count
            for (int mt = 0; mt < nmt; mt++) {
                int r0 = mt * 16 + gid;
                bool p0 = (r0 < m), p1 = (r0 + 8 < m);
                unsigned a[2][4];
#pragma unroll
                for (int kt = 0; kt < 2; kt++) {
                    a[kt][0] = f2tf(tf[r0       * 20 + kt * 8 + tig]);
                    a[kt][1] = f2tf(tf[(r0 + 8) * 20 + kt * 8 + tig]);
                    a[kt][2] = f2tf(tf[r0       * 20 + kt * 8 + tig + 4]);
                    a[kt][3] = f2tf(tf[(r0 + 8) * 20 + kt * 8 + tig + 4]);
                }
#pragma unroll
                for (int nt = 0; nt < 8; nt++) {
                    float d0 = 0.f, d1 = 0.f, d2 = 0.f, d3 = 0.f;
                    mma_tf32(d0, d1, d2, d3,
                             a[0][0], a[0][1], a[0][2], a[0][3],
                             Bf[nt][0][0], Bf[nt][0][1]);
                    mma_tf32(d0, d1, d2, d3,
                             a[1][0], a[1][1], a[1][2], a[1][3],
                             Bf[nt][1][0], Bf[nt][1][1]);
                    ull bp = *(const ull*)&sbias[nt * 8 + 2 * tig];
                    ull v0 = silu2(add2(pk2(d0, d1), bp));
                    ull v1 = silu2(add2(pk2(d2, d3), bp));
                    if (p0) acc[nt] = add2(acc[nt], v0);
                    if (p1) acc[nt] = add2(acc[nt], v1);
                }
            }
            __syncwarp();
        }

#pragma unroll
        for (int nt = 0; nt < 8; nt++) {
            float2 av = up2(acc[nt]);
#pragma unroll
            for (int d = 4; d < 32; d <<= 1) {
                av.x += __shfl_xor_sync(0xffffffffu, av.x, d);
                av.y += __shfl_xor_sync(0xffffffffu, av.y, d);
            }
            acc[nt] = pk2(av.x, av.y);
        }
        if (gid == 0) {
#pragma unroll
            for (int nt = 0; nt < 8; nt++)
                *(float2*)&g_S[(size_t)n * 64 + nt * 8 + 2 * tig] = up2(acc[nt]);
        }
    }
}

// ---------------------------------------------------------------------------
// 4b) self-loop fixup (rare).
// ---------------------------------------------------------------------------
__global__ void fixup_kernel(
    const float* __restrict__ rbf, const int* __restrict__ eidx,
    const float* __restrict__ W1, const float* __restrict__ b1, int E)
{
    int nsl = min(g_slN, 256);
    int w = threadIdx.x >> 5, lane = threadIdx.x & 31;
    for (int i = blockIdx.x * 8 + w; i < nsl; i += gridDim.x * 8) {
        int e = g_slE[i];
        int r = eidx[e];
        int c0 = 2 * lane, c1 = 2 * lane + 1;
        float h0 = b1[c0], h1 = b1[c1];
        for (int k = 0; k < 16; k++) {
            float f = rbf[(size_t)e * 16 + k];
            h0 = fmaf(f, W1[k * 64 + c0], h0);
            h1 = fmaf(f, W1[k * 64 + c1], h1);
        }
        float wa = W1[16 * 64 + c0], wb = W1[16 * 64 + c1];
        float d0 = fsilu_tanh(fmaf(PI_HALF, wa, h0)) -
                   fsilu_tanh(fmaf(ANG_A,  wa, h0));
        float d1 = fsilu_tanh(fmaf(PI_HALF, wb, h1)) -
                   fsilu_tanh(fmaf(ANG_A,  wb, h1));
        atomicAdd(&g_S[(size_t)r * 64 + c0], d0);
        atomicAdd(&g_S[(size_t)r * 64 + c1], d1);
    }
}

// ---------------------------------------------------------------------------
// 5) node: warp processes 8 nodes; 48KB weights in SMEM.
// ---------------------------------------------------------------------------
__global__ void __launch_bounds__(256) node_kernel(
    const float* __restrict__ x,
    const float* __restrict__ W2, const float* __restrict__ b2,
    const float* __restrict__ W3, const float* __restrict__ b3,
    const float* __restrict__ W4, const float* __restrict__ b4,
    float* __restrict__ out, int N)
{
    __shared__ __align__(16) float Ws[3 * 64 * 64];
    for (int i = threadIdx.x; i < 4096; i += 256) {
        Ws[i]        = W2[i];
        Ws[4096 + i] = W3[i];
        Ws[8192 + i] = W4[i];
    }
    __syncthreads();

    int lane = threadIdx.x & 31;
    int wid  = threadIdx.x >> 5;
    float2 bb2 = *(const float2*)&b2[2 * lane];
    float2 bb3 = *(const float2*)&b3[2 * lane];
    float2 bb4 = *(const float2*)&b4[2 * lane];

    for (int g = blockIdx.x * 8 + wid; g * 8 < N; g += gridDim.x * 8) {
        int n0 = g * 8;
        float2 v[8];
        float  dg[8];
#pragma unroll
        for (int t = 0; t < 8; t++) {
            int n = n0 + t;
            if (n < N) {
                v[t]  = *(const float2*)&g_S[(size_t)n * 64 + 2 * lane];
                dg[t] = (float)(g_off[n + 1] - g_off[n]);
            } else {
                v[t] = make_float2(0.f, 0.f); dg[t] = 0.f;
            }
        }

        float2 a[8];
#pragma unroll
        for (int t = 0; t < 8; t++)
            a[t] = make_float2(dg[t] * bb2.x, dg[t] * bb2.y);

#pragma unroll 4
        for (int kk = 0; kk < 32; kk++) {
            float2 w0 = *(const float2*)&Ws[(2 * kk)     * 64 + 2 * lane];
            float2 w1 = *(const float2*)&Ws[(2 * kk + 1) * 64 + 2 * lane];
#pragma unroll
            for (int t = 0; t < 8; t++) {
                float x0 = __shfl_sync(0xffffffffu, v[t].x, kk);
                float x1 = __shfl_sync(0xffffffffu, v[t].y, kk);
                a[t].x = fmaf(x0, w0.x, fmaf(x1, w1.x, a[t].x));
                a[t].y = fmaf(x0, w0.y, fmaf(x1, w1.y, a[t].y));
            }
        }

        float2 p[8];
#pragma unroll
        for (int t = 0; t < 8; t++) p[t] = bb3;
#pragma unroll 4
        for (int kk = 0; kk < 32; kk++) {
            float2 w0 = *(const float2*)&Ws[4096 + (2 * kk)     * 64 + 2 * lane];
            float2 w1 = *(const float2*)&Ws[4096 + (2 * kk + 1) * 64 + 2 * lane];
#pragma unroll
            for (int t = 0; t < 8; t++) {
                float x0 = __shfl_sync(0xffffffffu, a[t].x, kk);
                float x1 = __shfl_sync(0xffffffffu, a[t].y, kk);
                p[t].x = fmaf(x0, w0.x, fmaf(x1, w1.x, p[t].x));
                p[t].y = fmaf(x0, w0.y, fmaf(x1, w1.y, p[t].y));
            }
        }
#pragma unroll
        for (int t = 0; t < 8; t++) {
            p[t].x *= fsig(p[t].x);
            p[t].y *= fsig(p[t].y);
        }

        float2 q[8];
#pragma unroll
        for (int t = 0; t < 8; t++) q[t] = bb4;
#pragma unroll 4
        for (int kk = 0; kk < 32; kk++) {
            float2 w0 = *(const float2*)&Ws[8192 + (2 * kk)     * 64 + 2 * lane];
            float2 w1 = *(const float2*)&Ws[8192 + (2 * kk + 1) * 64 + 2 * lane];
#pragma unroll
            for (int t = 0; t < 8; t++) {
                float x0 = __shfl_sync(0xffffffffu, p[t].x, kk);
                float x1 = __shfl_sync(0xffffffffu, p[t].y, kk);
                q[t].x = fmaf(x0, w0.x, fmaf(x1, w1.x, q[t].x));
                q[t].y = fmaf(x0, w0.y, fmaf(x1, w1.y, q[t].y));
            }
        }
#pragma unroll
        for (int t = 0; t < 8; t++) {
            int n = n0 + t;
            if (n < N) {
                float2 xv = *(const float2*)&x[(size_t)n * 64 + 2 * lane];
                *(float2*)&out[(size_t)n * 64 + 2 * lane] =
                    make_float2(xv.x + q[t].x, xv.y + q[t].y);
            }
        }
    }
}

// ---------------------------------------------------------------------------
extern "C" void kernel_launch(void* const* d_in, const int* in_sizes, int n_in,
                              void* d_out, int out_size)
{
    const float* x   = (const float*)d_in[0];
    const float* rbf = (const float*)d_in[2];
    const int*   eidx = (const int*)d_in[3];
    const float* W1 = (const float*)d_in[4];
    const float* b1 = (const float*)d_in[5];
    const float* W2 = (const float*)d_in[6];
    const float* b2 = (const float*)d_in[7];
    const float* W3 = (const float*)d_in[8];
    const float* b3 = (const float*)d_in[9];
    const float* W4 = (const float*)d_in[10];
    const float* b4 = (const float*)d_in[11];
    float* out = (float*)d_out;

    int E = in_sizes[3] / 2;
    int N = in_sizes[0] / EMB;
    int nblk = (N + 511) / 512;

    hist_kernel<<<(E + 255) / 256, 256>>>(eidx, E);
    scan_kernel<<<nblk, 512>>>(N, E);
    permute_kernel<<<(E + 255) / 256, 256>>>(eidx, E);
    edge_gather_kernel<<<592, 256>>>(rbf, W1, b1, N);
    fixup_kernel<<<4, 256>>>(rbf, eidx, W1, b1, E);
    node_kernel<<<592, 256>>>(x, W2, b2, W3, b3, W4, b4, out, N);
}